// round 7
// baseline (speedup 1.0000x reference)
#include <cuda_runtime.h>

// GumbelVQ forward on GB300 (sm_103a).
//
//  - st = y_hard numerically  =>  z_q = embedding[argmax_k(logits + gumbel)]
//  - JAX (threefry_partitionable=True, the modern default) generates uniform
//    bits in COUNTER MODE: for linear element index i (row-major over (N,K)),
//      (o0, o1) = threefry2x32(key=(0,42), x0=hi32(i)=0, x1=lo32(i)=i)
//      bits     = o0 ^ o1                        (xor-fold for 32-bit draws)
//  - u = bitcast((bits>>9)|0x3f800000) - 1;  u = max(u, 1e-20)
//  - gumbel = -log(-log u); argmax first-occurrence (ties -> smaller k)
//  - Filter: g <= -log(1-u) <= -ilogb(1-u)*ln2, so only candidates that can
//    beat the warp's running max pay the exact logs (~10 per row of 8192).

#define NUM_CODES 8192
#define NROWS     8192

__device__ float g_row_commit[NROWS];
__device__ int   g_counts[NUM_CODES];

__device__ __forceinline__ unsigned rotl(unsigned x, int r) {
    return __funnelshift_l(x, x, r);
}

// threefry2x32, key (0,42), input (0, i), 20 rounds, output o0^o1.
// Key injections folded into the following round's 3-input add.
__device__ __forceinline__ unsigned tf_bits(unsigned i) {
    const unsigned C = 0x1BD11BF0u;          // 0 ^ 42 ^ 0x1BD11BDA
    unsigned x0, x1;
    x1 = i + 42u;                            // x1 = lo(i) + ks[1]
    x0 = x1;                                 // R1 add with x0 = 0 + ks[0] = 0
    x1 = rotl(x1, 13) ^ x0;
    x0 += x1; x1 = rotl(x1, 15) ^ x0;
    x0 += x1; x1 = rotl(x1, 26) ^ x0;
    x0 += x1; x1 = rotl(x1,  6) ^ x0;
    x1 += C + 1u;                            // inj1: x1 += ks[2]+1
    x0 += 42u + x1;                          // inj1: x0 += ks[1], folded
    x1 = rotl(x1, 17) ^ x0;
    x0 += x1; x1 = rotl(x1, 29) ^ x0;
    x0 += x1; x1 = rotl(x1, 16) ^ x0;
    x0 += x1; x1 = rotl(x1, 24) ^ x0;
    x1 += 2u;                                // inj2: x1 += ks[0]+2
    x0 += C + x1;                            // inj2: x0 += ks[2], folded
    x1 = rotl(x1, 13) ^ x0;
    x0 += x1; x1 = rotl(x1, 15) ^ x0;
    x0 += x1; x1 = rotl(x1, 26) ^ x0;
    x0 += x1; x1 = rotl(x1,  6) ^ x0;
    x1 += 45u;                               // inj3: x1 += ks[1]+3
    x0 += x1;                                // inj3: x0 += ks[0] = 0
    x1 = rotl(x1, 17) ^ x0;
    x0 += x1; x1 = rotl(x1, 29) ^ x0;
    x0 += x1; x1 = rotl(x1, 16) ^ x0;
    x0 += x1; x1 = rotl(x1, 24) ^ x0;
    x1 += C + 4u;                            // inj4: x1 += ks[2]+4
    x0 += 42u + x1;                          // inj4: x0 += ks[1], folded
    x1 = rotl(x1, 13) ^ x0;
    x0 += x1; x1 = rotl(x1, 15) ^ x0;
    x0 += x1; x1 = rotl(x1, 26) ^ x0;
    x0 += x1; x1 = rotl(x1,  6) ^ x0;
    return (x0 + C) ^ (x1 + 5u);             // inj5 (+C, +5) and xor-fold
}

// exact gumbel from f = 1+u in [1,2): winners have u~1, use log1p there so the
// inner log keeps full relative accuracy even under fast-math.
__device__ __forceinline__ float gumbel_exact(float f) {
    float u = fmaxf(f - 1.0f, 1e-20f);
    float e = (f > 1.5f) ? (-log1pf(f - 2.0f)) : (-logf(u));
    return -logf(e);
}

__global__ void vq_zero_kernel() {
    int t = blockIdx.x * blockDim.x + threadIdx.x;
    if (t < NUM_CODES) g_counts[t] = 0;
}

__global__ void __launch_bounds__(256) vq_argmax_kernel(
    const float* __restrict__ z_e,
    const float* __restrict__ emb,
    const float* __restrict__ proj,
    float* __restrict__ out,
    int has_idx)
{
    const int lane = threadIdx.x & 31;
    const int warp = threadIdx.x >> 5;
    const int n    = blockIdx.x * 8 + warp;       // one row per warp
    const int b    = n >> 10, hw = n & 1023;      // z_e is (8, 8, 32, 32)

    float z[8];
#pragma unroll
    for (int d = 0; d < 8; d++)
        z[d] = z_e[b * 8192 + d * 1024 + hw];

    const float NEG = -3.0e38f;
    float madj = NEG;                 // (warp running max) - slack
    float best = NEG;
    int   bi   = 0;
    const unsigned base = (unsigned)n * (unsigned)NUM_CODES + (unsigned)lane;
    const float4* __restrict__ proj4 = (const float4*)proj;

#pragma unroll 2
    for (int j = 0; j < NUM_CODES / 32; j++) {
        const int k = j * 32 + lane;
        const unsigned bits = tf_bits(base + (unsigned)(j * 32));
        // f = 1 + u in [1, 2);  v = 1 - u = 2 - f exactly (Sterbenz)
        const float f = __uint_as_float((bits >> 9) | 0x3f800000u);
        const float v = 2.0f - f;
        // ub(g) = -ilogb(v) * ln2_up ; int->float via exponent-bias trick
        const int   e  = 127 - (int)(__float_as_uint(v) >> 23);   // 0..23
        const float fe = __uint_as_float((unsigned)e | 0x4B000000u) - 8388608.0f;

        const float4 wa = __ldg(proj4 + k * 2);
        const float4 wb = __ldg(proj4 + k * 2 + 1);
        float l = z[0] * wa.x;
        l = fmaf(z[1], wa.y, l); l = fmaf(z[2], wa.z, l);
        l = fmaf(z[3], wa.w, l); l = fmaf(z[4], wb.x, l);
        l = fmaf(z[5], wb.y, l); l = fmaf(z[6], wb.z, l);
        l = fmaf(z[7], wb.w, l);

        // only elements that could beat the warp max pay the exact logs
        const bool p = fmaf(fe, 0.69314724f, l) > madj;
        if (__ballot_sync(0xffffffffu, p)) {
            float s = NEG;
            if (p) {
                s = l + gumbel_exact(f);
                if (s > best) { best = s; bi = k; }
            }
            float sm = s;
#pragma unroll
            for (int o = 16; o > 0; o >>= 1)
                sm = fmaxf(sm, __shfl_xor_sync(0xffffffffu, sm, o));
            if (sm > madj) madj = sm;     // madj <= true max; slack via ub's +0
        }
    }

    // cross-lane argmax; ties -> smaller k (first occurrence, jnp.argmax)
#pragma unroll
    for (int o = 16; o > 0; o >>= 1) {
        float ob = __shfl_xor_sync(0xffffffffu, best, o);
        int   oi = __shfl_xor_sync(0xffffffffu, bi,   o);
        if (ob > best || (ob == best && oi < bi)) { best = ob; bi = oi; }
    }

    // outputs: z_q gather, per-row commit sum, counts, idx
    float sq = 0.0f;
    if (lane < 8) {
        float ev = emb[bi * 8 + lane];
        out[b * 8192 + lane * 1024 + hw] = ev;
        float dd = z[lane] - ev;
        sq = dd * dd;
    }
#pragma unroll
    for (int o = 16; o > 0; o >>= 1)
        sq += __shfl_xor_sync(0xffffffffu, sq, o);
    if (lane == 0) {
        g_row_commit[n] = sq;
        atomicAdd(&g_counts[bi], 1);
        if (has_idx) out[65536 + n] = (float)bi;
    }
}

__global__ void __launch_bounds__(256) vq_final_kernel(float* __restrict__ out,
                                                       int has_scalars) {
    __shared__ float sp[256];
    __shared__ float sc[256];
    __shared__ int   su[256];
    const int t = threadIdx.x;
    float plog = 0.0f, csum = 0.0f;
    int used = 0;
    for (int k = t; k < NUM_CODES; k += 256) {
        int c = g_counts[k];
        if (c > 0) {
            float avg = (float)c * (1.0f / 8192.0f);
            plog += avg * logf(avg + 1e-10f);
            used++;
        }
        csum += g_row_commit[k];      // NROWS == NUM_CODES == 8192
    }
    sp[t] = plog; sc[t] = csum; su[t] = used;
    __syncthreads();
    for (int s = 128; s > 0; s >>= 1) {
        if (t < s) { sp[t] += sp[t + s]; sc[t] += sc[t + s]; su[t] += su[t + s]; }
        __syncthreads();
    }
    if (t == 0 && has_scalars) {
        out[73728] = 0.25f * (sc[0] * (1.0f / 65536.0f));  // commit_loss
        out[73729] = expf(-sp[0]);                         // perplexity
        out[73730] = (float)su[0] * (1.0f / 8192.0f);      // usage
    }
}

extern "C" void kernel_launch(void* const* d_in, const int* in_sizes, int n_in,
                              void* d_out, int out_size) {
    const float* z_e  = (const float*)d_in[0];
    const float* emb  = (const float*)d_in[1];
    const float* proj = (const float*)d_in[2];
    float* out = (float*)d_out;
    int has_idx     = (out_size >= 65536 + 8192) ? 1 : 0;
    int has_scalars = (out_size >= 65536 + 8192 + 3) ? 1 : 0;

    vq_zero_kernel<<<(NUM_CODES + 255) / 256, 256>>>();
    vq_argmax_kernel<<<NROWS / 8, 256>>>(z_e, emb, proj, out, has_idx);
    vq_final_kernel<<<1, 256>>>(out, has_scalars);
}